// round 2
// baseline (speedup 1.0000x reference)
#include <cuda_runtime.h>
#include <cstdint>

// RandomBitFlip: bit-exact reproduction of JAX threefry2x32 random bit flips,
// PARTITIONABLE mode (jax_threefry_partitionable=True, default in modern JAX):
//   per element i: (o0,o1) = threefry2x32(subkey, hi32(i)=0, lo32(i)=i)
//   draw word     = o0 ^ o1                      (bit_width==32 path)
//   mask          = AND of 14 draw words         (absorbing -> early exit)
// Subkeys: fold_in(key(seed), s) = threefry2x32(key, (0, s))  [host-side].

#define NH 14  // PROB_HALVES

struct KeysParam {
    uint32_t ke0[NH], ke1[NH];  // exp-stream subkeys (k0, k1)
    uint32_t kf0[NH], kf1[NH];  // frac-stream subkeys
};

// ---------------- Threefry-2x32-20 (KAT-verified vs Random123) --------------

__device__ __forceinline__ uint32_t tf2x32_word(uint32_t k0, uint32_t k1,
                                                uint32_t ctr) {
    // counter = (x0=0, x1=ctr); returns o0 ^ o1 (partitionable 32-bit draw)
    const uint32_t ks2 = k0 ^ k1 ^ 0x1BD11BDAu;
    uint32_t x0 = k0;          // 0 + k0
    uint32_t x1 = ctr + k1;
#define TF_R(r) { x0 += x1; x1 = __funnelshift_l(x1, x1, (r)); x1 ^= x0; }
    TF_R(13) TF_R(15) TF_R(26) TF_R(6)   x0 += k1;  x1 += ks2 + 1u;
    TF_R(17) TF_R(29) TF_R(16) TF_R(24)  x0 += ks2; x1 += k0 + 2u;
    TF_R(13) TF_R(15) TF_R(26) TF_R(6)   x0 += k0;  x1 += k1 + 3u;
    TF_R(17) TF_R(29) TF_R(16) TF_R(24)  x0 += k1;  x1 += ks2 + 4u;
    TF_R(13) TF_R(15) TF_R(26) TF_R(6)   x0 += ks2; x1 += k0 + 5u;
#undef TF_R
    return x0 ^ x1;
}

// ---------------- Main kernel: one thread per element -----------------------

__global__ void __launch_bounds__(256)
rbf_kernel(const float* __restrict__ x, float* __restrict__ out,
           uint32_t n, KeysParam K) {
    uint32_t i = blockIdx.x * 256u + threadIdx.x;
    if (i >= n) return;

    // exp-stream mask: AND of 14 partitionable draws, absorbing early exit
    uint32_t aE = 0xFFFFFFFFu;
#pragma unroll 1
    for (int s = 0; s < NH; ++s) {
        aE &= tf2x32_word(K.ke0[s], K.ke1[s], i);
        if (aE == 0u) break;
    }

    // frac-stream mask
    uint32_t aF = 0xFFFFFFFFu;
#pragma unroll 1
    for (int s = 0; s < NH; ++s) {
        aF &= tf2x32_word(K.kf0[s], K.kf1[s], i);
        if (aF == 0u) break;
    }

    const uint32_t EXPM = 0xFF800000u, FRACM = 0x007FFFFFu;
    uint32_t u = __float_as_uint(x[i]) ^ (aE & EXPM) ^ (aF & FRACM);

    // zero_out_invalid: non-finite iff exponent field is all ones
    out[i] = (((u >> 23) & 0xFFu) == 0xFFu) ? 0.0f : __uint_as_float(u);
}

// ---------------- Host-side key derivation (fold_in) ------------------------

static void host_tf2x32(uint32_t k0, uint32_t k1, uint32_t x0, uint32_t x1,
                        uint32_t* o0, uint32_t* o1) {
    static const uint32_t R0[4] = {13, 15, 26, 6}, R1[4] = {17, 29, 16, 24};
    uint32_t ks[3] = {k0, k1, k0 ^ k1 ^ 0x1BD11BDAu};
    x0 += ks[0]; x1 += ks[1];
    for (int i = 0; i < 5; ++i) {
        const uint32_t* R = (i & 1) ? R1 : R0;
        for (int r = 0; r < 4; ++r) {
            x0 += x1;
            x1 = (x1 << R[r]) | (x1 >> (32u - R[r]));
            x1 ^= x0;
        }
        x0 += ks[(i + 1) % 3];
        x1 += ks[(i + 2) % 3] + (uint32_t)(i + 1);
    }
    *o0 = x0; *o1 = x1;
}

extern "C" void kernel_launch(void* const* d_in, const int* in_sizes, int n_in,
                              void* d_out, int out_size) {
    (void)n_in; (void)in_sizes;
    // fold_in(key(seed), s) = threefry2x32(key, (0, s)); key(seed) = (0, seed)
    KeysParam K;
    const uint32_t seed_exp = 42u, seed_frac = 42u + 10007u;  // 10049
    for (int s = 0; s < NH; ++s) {
        host_tf2x32(0u, seed_exp,  0u, (uint32_t)s, &K.ke0[s], &K.ke1[s]);
        host_tf2x32(0u, seed_frac, 0u, (uint32_t)s, &K.kf0[s], &K.kf1[s]);
    }

    const float* x = (const float*)d_in[0];
    float* out = (float*)d_out;
    uint32_t n = (uint32_t)out_size;  // 16*4096*1024 = 67108864

    uint32_t blocks = (n + 255u) / 256u;
    rbf_kernel<<<blocks, 256>>>(x, out, n, K);
}

// round 4
// speedup vs baseline: 1.3274x; 1.3274x over previous
#include <cuda_runtime.h>
#include <cstdint>

// RandomBitFlip — JAX threefry2x32, partitionable mode, bit-exact.
//   per element i: draw_s = o0^o1 of threefry2x32(fold_in(key(seed),s), (0,i))
//   mask = AND of 14 draws; exp stream masked by 0xFF800000, frac by 0x007FFFFF.
// R3: fix constexpr host/device qualification (no --expt-relaxed-constexpr in
// harness build). Otherwise identical to R2: adds forced onto the FMA pipe
// (IMAD via mad.lo with runtime 'one'), compile-time subkeys as immediates,
// mask-aware early exit, fused AND-accumulate LOP3.

#define NH 14  // PROB_HALVES

// ---------------- compile-time threefry (subkey derivation) -----------------

__host__ __device__ constexpr uint32_t rotl_c(uint32_t v, int r) {
    return (v << r) | (v >> (32 - r));
}

__host__ __device__ constexpr uint64_t tf_c(uint32_t k0, uint32_t k1,
                                            uint32_t x0, uint32_t x1) {
    uint32_t ks2 = k0 ^ k1 ^ 0x1BD11BDAu;
    uint32_t ks[3] = {k0, k1, ks2};
    int R0[4] = {13, 15, 26, 6}, R1[4] = {17, 29, 16, 24};
    x0 += k0; x1 += k1;
    for (int b = 0; b < 5; ++b) {
        for (int r = 0; r < 4; ++r) {
            int rr = (b & 1) ? R1[r] : R0[r];
            x0 += x1; x1 = rotl_c(x1, rr); x1 ^= x0;
        }
        x0 += ks[(b + 1) % 3];
        x1 += ks[(b + 2) % 3] + (uint32_t)(b + 1);
    }
    return (uint64_t)x0 | ((uint64_t)x1 << 32);
}
// fold_in(key(seed), s) = threefry2x32((0,seed), (0,s))
__host__ __device__ constexpr uint64_t foldin(uint32_t seed, int s) {
    return tf_c(0u, seed, 0u, (uint32_t)s);
}

// ---------------- device draw: one threefry, adds on the FMA pipe -----------

// d = a + b, both registers, as IMAD (fma pipe): d = a*one + b
#define ADD_RR(d, a, b) \
    asm("mad.lo.u32 %0, %1, %2, %3;" : "=r"(d) : "r"(a), "r"(one), "r"(b))
// d = a + K (immediate), as IMAD: d = one*K + a
#define ADD_RI(d, a, K) \
    asm("mad.lo.u32 %0, %1, %2, %3;" : "=r"(d) : "r"(one), "n"((int)(K)), "r"(a))

template<uint32_t K0, uint32_t K1>
__device__ __forceinline__ uint32_t tfdraw(uint32_t i, uint32_t one) {
    constexpr uint32_t KS2 = K0 ^ K1 ^ 0x1BD11BDAu;
    uint32_t x0, x1;
    ADD_RI(x1, i, K1);       // x1 = i + K1        (counter injection)
    ADD_RI(x0, x1, K0);      // x0 = K0 + x1       (x0-init folded with round-1 add)
    x1 = __funnelshift_l(x1, x1, 13) ^ x0;
#define RND(r) { ADD_RR(x0, x1, x0); x1 = __funnelshift_l(x1, x1, (r)) ^ x0; }
    RND(15) RND(26) RND(6)
    ADD_RI(x0, x0, K1);  ADD_RI(x1, x1, KS2 + 1u);
    RND(17) RND(29) RND(16) RND(24)
    ADD_RI(x0, x0, KS2); ADD_RI(x1, x1, K0 + 2u);
    RND(13) RND(15) RND(26) RND(6)
    ADD_RI(x0, x0, K0);  ADD_RI(x1, x1, K1 + 3u);
    RND(17) RND(29) RND(16) RND(24)
    ADD_RI(x0, x0, K1);  ADD_RI(x1, x1, KS2 + 4u);
    RND(13) RND(15) RND(26) RND(6)
    ADD_RI(x0, x0, KS2); ADD_RI(x1, x1, K0 + 5u);
#undef RND
    return x0 ^ x1;      // fuses with caller's AND into one LOP3
}

// ---------------- 14-draw AND-accumulate with mask-aware early exit ---------

template<uint32_t SEED, uint32_t MASK, int S>
__device__ __forceinline__ void accum(uint32_t i, uint32_t one, uint32_t &a) {
    if constexpr (S < NH) {
        constexpr uint64_t kk = foldin(SEED, S);
        a &= tfdraw<(uint32_t)(kk & 0xFFFFFFFFu), (uint32_t)(kk >> 32)>(i, one);
        if constexpr (S >= 5) {          // exit prob ~0 before draw 6; skip checks
            if ((a & MASK) == 0u) return;
        }
        accum<SEED, MASK, S + 1>(i, one, a);
    }
}

// ---------------- main kernel ----------------------------------------------

__global__ void __launch_bounds__(256)
rbf_kernel(const float* __restrict__ x, float* __restrict__ out,
           uint32_t n, uint32_t one) {
    uint32_t i = blockIdx.x * 256u + threadIdx.x;
    if (i >= n) return;

    uint32_t xin = __float_as_uint(x[i]);   // issue LDG early; hidden under PRNG

    constexpr uint32_t EXPM = 0xFF800000u, FRACM = 0x007FFFFFu;
    uint32_t aE = 0xFFFFFFFFu, aF = 0xFFFFFFFFu;
    accum<42u,          EXPM,  0>(i, one, aE);   // seed_exp  = 42
    accum<42u + 10007u, FRACM, 0>(i, one, aF);   // seed_frac = 10049

    uint32_t u = xin ^ (aE & EXPM) ^ (aF & FRACM);
    // zero_out_invalid: non-finite iff exponent field is all ones
    out[i] = (((u >> 23) & 0xFFu) == 0xFFu) ? 0.0f : __uint_as_float(u);
}

extern "C" void kernel_launch(void* const* d_in, const int* in_sizes, int n_in,
                              void* d_out, int out_size) {
    (void)n_in; (void)in_sizes;
    const float* x = (const float*)d_in[0];
    float* out = (float*)d_out;
    uint32_t n = (uint32_t)out_size;           // 16*4096*1024 = 67108864
    uint32_t blocks = (n + 255u) / 256u;
    rbf_kernel<<<blocks, 256>>>(x, out, n, 1u);
}

// round 5
// speedup vs baseline: 1.7454x; 1.3149x over previous
#include <cuda_runtime.h>
#include <cstdint>

// RandomBitFlip — JAX threefry2x32, partitionable mode, bit-exact.
// R5: two-phase survivor compaction.
//   Phase A: 6 draws/stream dense; survivors (masked partial != 0) pushed to
//            compacted lists. out[i] = x[i] bits (final for ~69% of elements).
//   Phase B-frac: completes frac mask for 30.4% survivors, XORs into out.
//   Phase B-exp (last): completes exp mask for 13.2% survivors, XORs, and
//            applies finite-zeroing (finiteness depends only on exp stream).
// Adds stay on the FMA pipe (IMAD via mad.lo with runtime 'one').

#define NH 14           // PROB_HALVES
#define SDENSE 6        // dense draws per stream in phase A
#define EXPM  0xFF800000u
#define FRACM 0x007FFFFFu

static constexpr uint32_t CAP_E = 9600000u;    // expected 8.87M  (+260 sigma)
static constexpr uint32_t CAP_F = 21200000u;   // expected 20.39M (+290 sigma)

__device__ uint2 g_se[CAP_E];   // exp survivors: {index, partial mask}
__device__ uint2 g_sf[CAP_F];   // frac survivors
__device__ unsigned int g_cnt[2];

// ---------------- compile-time threefry (subkey derivation) -----------------

__host__ __device__ constexpr uint32_t rotl_c(uint32_t v, int r) {
    return (v << r) | (v >> (32 - r));
}

__host__ __device__ constexpr uint64_t tf_c(uint32_t k0, uint32_t k1,
                                            uint32_t x0, uint32_t x1) {
    uint32_t ks2 = k0 ^ k1 ^ 0x1BD11BDAu;
    uint32_t ks[3] = {k0, k1, ks2};
    int R0[4] = {13, 15, 26, 6}, R1[4] = {17, 29, 16, 24};
    x0 += k0; x1 += k1;
    for (int b = 0; b < 5; ++b) {
        for (int r = 0; r < 4; ++r) {
            int rr = (b & 1) ? R1[r] : R0[r];
            x0 += x1; x1 = rotl_c(x1, rr); x1 ^= x0;
        }
        x0 += ks[(b + 1) % 3];
        x1 += ks[(b + 2) % 3] + (uint32_t)(b + 1);
    }
    return (uint64_t)x0 | ((uint64_t)x1 << 32);
}
__host__ __device__ constexpr uint64_t foldin(uint32_t seed, int s) {
    return tf_c(0u, seed, 0u, (uint32_t)s);
}

// ---------------- device draw: one threefry, adds on the FMA pipe -----------

#define ADD_RR(d, a, b) \
    asm("mad.lo.u32 %0, %1, %2, %3;" : "=r"(d) : "r"(a), "r"(one), "r"(b))
#define ADD_RI(d, a, K) \
    asm("mad.lo.u32 %0, %1, %2, %3;" : "=r"(d) : "r"(one), "n"((int)(K)), "r"(a))

template<uint32_t K0, uint32_t K1>
__device__ __forceinline__ uint32_t tfdraw(uint32_t i, uint32_t one) {
    constexpr uint32_t KS2 = K0 ^ K1 ^ 0x1BD11BDAu;
    uint32_t x0, x1;
    ADD_RI(x1, i, K1);
    ADD_RI(x0, x1, K0);
    x1 = __funnelshift_l(x1, x1, 13) ^ x0;
#define RND(r) { ADD_RR(x0, x1, x0); x1 = __funnelshift_l(x1, x1, (r)) ^ x0; }
    RND(15) RND(26) RND(6)
    ADD_RI(x0, x0, K1);  ADD_RI(x1, x1, KS2 + 1u);
    RND(17) RND(29) RND(16) RND(24)
    ADD_RI(x0, x0, KS2); ADD_RI(x1, x1, K0 + 2u);
    RND(13) RND(15) RND(26) RND(6)
    ADD_RI(x0, x0, K0);  ADD_RI(x1, x1, K1 + 3u);
    RND(17) RND(29) RND(16) RND(24)
    ADD_RI(x0, x0, K1);  ADD_RI(x1, x1, KS2 + 4u);
    RND(13) RND(15) RND(26) RND(6)
    ADD_RI(x0, x0, KS2); ADD_RI(x1, x1, K0 + 5u);
#undef RND
    return x0 ^ x1;
}

// AND-accumulate draws S..SEND-1; early-exit checks from draw CHECKFROM on.
template<uint32_t SEED, uint32_t MASK, int S, int SEND, int CHECKFROM>
__device__ __forceinline__ void accum(uint32_t i, uint32_t one, uint32_t &a) {
    if constexpr (S < SEND) {
        constexpr uint64_t kk = foldin(SEED, S);
        a &= tfdraw<(uint32_t)(kk & 0xFFFFFFFFu), (uint32_t)(kk >> 32)>(i, one);
        if constexpr (S >= CHECKFROM) {
            if ((a & MASK) == 0u) return;
        }
        accum<SEED, MASK, S + 1, SEND, CHECKFROM>(i, one, a);
    }
}

// ---------------- kernels ---------------------------------------------------

__global__ void zero_counters() {
    if (threadIdx.x < 2) g_cnt[threadIdx.x] = 0u;
}

__global__ void __launch_bounds__(256)
phaseA(const float* __restrict__ x, float* __restrict__ out,
       uint32_t n, uint32_t one) {
    uint32_t i = blockIdx.x * 256u + threadIdx.x;
    bool valid = (i < n);

    uint32_t pE = 0xFFFFFFFFu, pF = 0xFFFFFFFFu;
    if (valid) {
        uint32_t xin = __float_as_uint(x[i]);
        accum<42u,          EXPM,  0, SDENSE, 99>(i, one, pE);
        accum<42u + 10007u, FRACM, 0, SDENSE, 99>(i, one, pF);
        // Final value for elements where both streams die; survivors fixed in B.
        reinterpret_cast<uint32_t*>(out)[i] = xin;
    }

    // Block-aggregated survivor compaction (2 global atomics per block).
    __shared__ unsigned shc[2], shb[2];
    if (threadIdx.x < 2) shc[threadIdx.x] = 0u;
    __syncthreads();

    unsigned lane = threadIdx.x & 31u;
    bool sE = valid && ((pE & EXPM) != 0u);
    bool sF = valid && ((pF & FRACM) != 0u);
    unsigned mE = __ballot_sync(0xFFFFFFFFu, sE);
    unsigned mF = __ballot_sync(0xFFFFFFFFu, sF);
    unsigned wbE = 0u, wbF = 0u;
    if (lane == 0u) {
        if (mE) wbE = atomicAdd(&shc[0], (unsigned)__popc(mE));
        if (mF) wbF = atomicAdd(&shc[1], (unsigned)__popc(mF));
    }
    wbE = __shfl_sync(0xFFFFFFFFu, wbE, 0);
    wbF = __shfl_sync(0xFFFFFFFFu, wbF, 0);
    __syncthreads();
    if (threadIdx.x < 2) shb[threadIdx.x] = atomicAdd(&g_cnt[threadIdx.x], shc[threadIdx.x]);
    __syncthreads();

    unsigned lanebits = (1u << lane) - 1u;
    if (sE) {
        unsigned slot = shb[0] + wbE + (unsigned)__popc(mE & lanebits);
        if (slot < CAP_E) g_se[slot] = make_uint2(i, pE);
    }
    if (sF) {
        unsigned slot = shb[1] + wbF + (unsigned)__popc(mF & lanebits);
        if (slot < CAP_F) g_sf[slot] = make_uint2(i, pF);
    }
}

__global__ void __launch_bounds__(256)
phaseBfrac(float* __restrict__ out, uint32_t one) {
    uint32_t t = blockIdx.x * 256u + threadIdx.x;
    uint32_t cnt = g_cnt[1]; if (cnt > CAP_F) cnt = CAP_F;
    if (t >= cnt) return;
    uint2 e = g_sf[t];
    uint32_t p = e.y;
    accum<42u + 10007u, FRACM, SDENSE, NH, SDENSE>(e.x, one, p);
    uint32_t* ob = reinterpret_cast<uint32_t*>(out);
    ob[e.x] ^= (p & FRACM);        // frac flips never affect finiteness
}

__global__ void __launch_bounds__(256)
phaseBexp(float* __restrict__ out, uint32_t one) {
    uint32_t t = blockIdx.x * 256u + threadIdx.x;
    uint32_t cnt = g_cnt[0]; if (cnt > CAP_E) cnt = CAP_E;
    if (t >= cnt) return;
    uint2 e = g_se[t];
    uint32_t p = e.y;
    accum<42u, EXPM, SDENSE, NH, SDENSE>(e.x, one, p);
    uint32_t* ob = reinterpret_cast<uint32_t*>(out);
    uint32_t u = ob[e.x] ^ (p & EXPM);
    // zero_out_invalid: non-finite iff exponent field all ones (exp stream only)
    ob[e.x] = (((u >> 23) & 0xFFu) == 0xFFu) ? 0u : u;   // 0u == 0.0f bits
}

extern "C" void kernel_launch(void* const* d_in, const int* in_sizes, int n_in,
                              void* d_out, int out_size) {
    (void)n_in; (void)in_sizes;
    const float* x = (const float*)d_in[0];
    float* out = (float*)d_out;
    uint32_t n = (uint32_t)out_size;           // 16*4096*1024 = 67108864

    zero_counters<<<1, 32>>>();
    phaseA<<<(n + 255u) / 256u, 256>>>(x, out, n, 1u);
    phaseBfrac<<<(CAP_F + 255u) / 256u, 256>>>(out, 1u);   // must run before exp
    phaseBexp <<<(CAP_E + 255u) / 256u, 256>>>(out, 1u);   // finite-zero last
}